// round 5
// baseline (speedup 1.0000x reference)
#include <cuda_runtime.h>
#include <cstdint>

// LIF-MC-Refrac hybrid kernel (R5):
//   role 0: couple = v @ g.T, packed fp32 FFMA2, warp tile 64x32 (L1-traffic-min)
//           -> z, v, rho epilogue
//   role 1: i_new = i_decayed + inp@Wi.T + z@Wr.T, TF32 mma.sync, LDS.128 frags
//           -> i epilogue

namespace {
constexpr int Bd = 4096;
constexpr int Hd = 2048;
constexpr int Kd = 2048;

constexpr int BM = 128, BN = 128, BK = 16;
constexpr int NTHREADS = 256;
constexpr int SSTR = BK + 4;          // mma smem row stride (words)

constexpr float DT_TAU_MEM = 0.1f;
constexpr float DT_TAU_SYN = 0.2f;
constexpr float V_TH_C     = 1.0f;
constexpr float RHO_RST    = 5.0f;

constexpr int SMEM_BYTES = 2 * 128 * SSTR * 4;   // 20480 >= simt 16896
}

// ---- packed f32x2 helpers ----
__device__ __forceinline__ unsigned long long packf2(float lo, float hi) {
    unsigned long long r;
    asm("mov.b64 %0, {%1, %2};" : "=l"(r) : "f"(lo), "f"(hi));
    return r;
}
__device__ __forceinline__ unsigned long long dupf2(float x) {
    unsigned long long r;
    asm("mov.b64 %0, {%1, %1};" : "=l"(r) : "f"(x));
    return r;
}
__device__ __forceinline__ void ffma2(unsigned long long& d,
                                      unsigned long long a, unsigned long long b) {
    asm("fma.rn.f32x2 %0, %1, %2, %0;" : "+l"(d) : "l"(a), "l"(b));
}
__device__ __forceinline__ void unpackf2(unsigned long long v, float& lo, float& hi) {
    asm("mov.b64 {%0, %1}, %2;" : "=f"(lo), "=f"(hi) : "l"(v));
}

__device__ __forceinline__ uint32_t f2tf32(float x) {
    uint32_t r;
    asm("cvt.rna.tf32.f32 %0, %1;" : "=r"(r) : "f"(x));
    return r;
}

__device__ __forceinline__ void mma_tf32(float& c0, float& c1, float& c2, float& c3,
                                         uint32_t a0, uint32_t a1, uint32_t a2, uint32_t a3,
                                         uint32_t b0, uint32_t b1)
{
    asm volatile(
        "mma.sync.aligned.m16n8k8.row.col.f32.tf32.tf32.f32 "
        "{%0,%1,%2,%3},{%4,%5,%6,%7},{%8,%9},{%0,%1,%2,%3};"
        : "+f"(c0), "+f"(c1), "+f"(c2), "+f"(c3)
        : "r"(a0), "r"(a1), "r"(a2), "r"(a3), "r"(b0), "r"(b1));
}

__device__ __forceinline__ void lif_elem(float v, float i, float rho, float couple,
                                         float& z_out, float& v_out, float& rho_out)
{
    float dv    = DT_TAU_MEM * ((0.0f - v) + i);
    float v_dec = (v + dv) + couple;
    float z     = (v_dec - V_TH_C) > 0.0f ? 1.0f : 0.0f;
    float v_new = (1.0f - z) * v_dec;
    float mask  = rho > 0.0f ? 1.0f : 0.0f;
    v_new = (1.0f - mask) * v_new + mask * v;
    z     = (1.0f - mask) * z;
    rho_out = (1.0f - z) * fmaxf(rho - mask, 0.0f) + z * RHO_RST;
    z_out = z;
    v_out = v_new;
}

// ---------------- role 0: packed-fp32 coupling GEMM (warp 64x32) -------------
__device__ void coupling_simt(
    unsigned char* smem_raw, int bx, int by,
    const float* __restrict__ A0, const float* __restrict__ W0,
    const float* __restrict__ vin, const float* __restrict__ iin,
    const float* __restrict__ rhoin,
    float* __restrict__ out_z, float* __restrict__ out_v, float* __restrict__ out_rho)
{
    float* As = (float*)smem_raw;                 // [BK][BM+4]
    float* Bs = As + BK * (BM + 4);               // [BK][BN+4]
    constexpr int AST = BM + 4;

    const int tid  = threadIdx.x;
    const int warp = tid >> 5;
    const int lane = tid & 31;
    const int wM   = warp >> 2;        // 0..1 -> 64 rows
    const int wN   = warp & 3;         // 0..3 -> 32 cols
    const int rg   = lane & 7;         // 8 row groups
    const int cg   = lane >> 3;        // 4 col groups
    const int rowb = wM * 64 + rg * 8; // smem m base
    const int colb = wN * 32 + cg * 8; // smem n base

    const int loadRow = tid >> 2;
    const int loadK   = (tid & 3) << 2;

    unsigned long long acc2[4][8];     // M-pairs x 8 cols
#pragma unroll
    for (int a = 0; a < 4; ++a)
#pragma unroll
        for (int b = 0; b < 8; ++b) acc2[a][b] = 0ull;

    const float* aPtr = A0 + (size_t)(by * BM + loadRow) * Kd + loadK;
    const float* wPtr = W0 + (size_t)(bx * BN + loadRow) * Kd + loadK;

    float4 ra0 = *(const float4*)(aPtr);
    float4 ra1 = *(const float4*)(aPtr + (size_t)64 * Kd);
    float4 rb0 = *(const float4*)(wPtr);
    float4 rb1 = *(const float4*)(wPtr + (size_t)64 * Kd);

    for (int kt = 0; kt < Kd; kt += BK) {
        __syncthreads();
        As[(loadK + 0) * AST + loadRow]      = ra0.x;
        As[(loadK + 1) * AST + loadRow]      = ra0.y;
        As[(loadK + 2) * AST + loadRow]      = ra0.z;
        As[(loadK + 3) * AST + loadRow]      = ra0.w;
        As[(loadK + 0) * AST + loadRow + 64] = ra1.x;
        As[(loadK + 1) * AST + loadRow + 64] = ra1.y;
        As[(loadK + 2) * AST + loadRow + 64] = ra1.z;
        As[(loadK + 3) * AST + loadRow + 64] = ra1.w;
        Bs[(loadK + 0) * AST + loadRow]      = rb0.x;
        Bs[(loadK + 1) * AST + loadRow]      = rb0.y;
        Bs[(loadK + 2) * AST + loadRow]      = rb0.z;
        Bs[(loadK + 3) * AST + loadRow]      = rb0.w;
        Bs[(loadK + 0) * AST + loadRow + 64] = rb1.x;
        Bs[(loadK + 1) * AST + loadRow + 64] = rb1.y;
        Bs[(loadK + 2) * AST + loadRow + 64] = rb1.z;
        Bs[(loadK + 3) * AST + loadRow + 64] = rb1.w;
        __syncthreads();

        if (kt + BK < Kd) {
            aPtr += BK; wPtr += BK;
            ra0 = *(const float4*)(aPtr);
            ra1 = *(const float4*)(aPtr + (size_t)64 * Kd);
            rb0 = *(const float4*)(wPtr);
            rb1 = *(const float4*)(wPtr + (size_t)64 * Kd);
        }

#pragma unroll
        for (int k = 0; k < BK; ++k) {
            float4 a0 = *(const float4*)&As[k * AST + rowb];
            float4 a1 = *(const float4*)&As[k * AST + rowb + 4];
            float4 b0 = *(const float4*)&Bs[k * AST + colb];
            float4 b1 = *(const float4*)&Bs[k * AST + colb + 4];

            unsigned long long ap[4];
            ap[0] = packf2(a0.x, a0.y);
            ap[1] = packf2(a0.z, a0.w);
            ap[2] = packf2(a1.x, a1.y);
            ap[3] = packf2(a1.z, a1.w);

            float bf[8] = {b0.x, b0.y, b0.z, b0.w, b1.x, b1.y, b1.z, b1.w};
#pragma unroll
            for (int b = 0; b < 8; ++b) {
                unsigned long long bb = dupf2(bf[b]);
                ffma2(acc2[0][b], ap[0], bb);
                ffma2(acc2[1][b], ap[1], bb);
                ffma2(acc2[2][b], ap[2], bb);
                ffma2(acc2[3][b], ap[3], bb);
            }
        }
    }

    float acc[8][8];
#pragma unroll
    for (int p = 0; p < 4; ++p)
#pragma unroll
        for (int b = 0; b < 8; ++b)
            unpackf2(acc2[p][b], acc[2 * p][b], acc[2 * p + 1][b]);

    const int row0 = by * BM + rowb;
    const int col0 = bx * BN + colb;
#pragma unroll
    for (int a = 0; a < 8; ++a) {
        const size_t base = (size_t)(row0 + a) * Hd + col0;
#pragma unroll
        for (int b = 0; b < 8; b += 4) {
            float4 vv = *(const float4*)(vin + base + b);
            float4 iv = *(const float4*)(iin + base + b);
            float4 rv = *(const float4*)(rhoin + base + b);
            float4 oz, ov, orh;
            lif_elem(vv.x, iv.x, rv.x, acc[a][b + 0], oz.x, ov.x, orh.x);
            lif_elem(vv.y, iv.y, rv.y, acc[a][b + 1], oz.y, ov.y, orh.y);
            lif_elem(vv.z, iv.z, rv.z, acc[a][b + 2], oz.z, ov.z, orh.z);
            lif_elem(vv.w, iv.w, rv.w, acc[a][b + 3], oz.w, ov.w, orh.w);
            *(float4*)(out_z   + base + b) = oz;
            *(float4*)(out_v   + base + b) = ov;
            *(float4*)(out_rho + base + b) = orh;
        }
    }
}

// ---------------- role 1: TF32 MMA i-path, LDS.128 fragment layout ------------
// smem word position within each 16-k row: pos(k) = 4*(k&3) + (k>>2).
// A uint4 at row*SSTR + 4q then holds k = {q, q+4, q+8, q+12} -> both ks halves
// of the m16n8k8 fragment in ONE LDS.128.
__device__ void ipath_mma(
    unsigned char* smem_raw, int bx, int by,
    const float* __restrict__ A0, const float* __restrict__ W0,
    const float* __restrict__ A1, const float* __restrict__ W1,
    const float* __restrict__ iin, float* __restrict__ out_i)
{
    uint32_t* Ahi = (uint32_t*)smem_raw;
    uint32_t* Bhi = Ahi + BM * SSTR;

    const int tid  = threadIdx.x;
    const int warp = tid >> 5;
    const int lane = tid & 31;
    const int g    = lane >> 2;
    const int q    = lane & 3;
    const int wM   = warp >> 2;
    const int wN   = warp & 3;

    const int loadRow = tid >> 2;
    const int loadK   = (tid & 3) << 2;
    const int t       = tid & 3;          // k>>2 of this loader's 4 words

    float acc[4][4][4];
#pragma unroll
    for (int mt = 0; mt < 4; ++mt)
#pragma unroll
        for (int nt = 0; nt < 4; ++nt)
#pragma unroll
            for (int r = 0; r < 4; ++r) acc[mt][nt][r] = 0.0f;

    // store positions: word j (k = loadK+j) -> 4*j + t
    const int d0 = t, d1 = 4 + t, d2 = 8 + t, d3 = 12 + t;

#pragma unroll
    for (int p = 0; p < 2; ++p) {
        const float* Amat = (p == 0) ? A0 : A1;
        const float* Wmat = (p == 0) ? W0 : W1;
        const float* aPtr = Amat + (size_t)(by * BM + loadRow) * Kd + loadK;
        const float* wPtr = Wmat + (size_t)(bx * BN + loadRow) * Kd + loadK;

        float4 ra0 = *(const float4*)(aPtr);
        float4 ra1 = *(const float4*)(aPtr + (size_t)64 * Kd);
        float4 rb0 = *(const float4*)(wPtr);
        float4 rb1 = *(const float4*)(wPtr + (size_t)64 * Kd);

        for (int kt = 0; kt < Kd; kt += BK) {
            __syncthreads();
            {
                int r0 = loadRow * SSTR;
                int r1 = (loadRow + 64) * SSTR;
                Ahi[r0 + d0] = f2tf32(ra0.x);
                Ahi[r0 + d1] = f2tf32(ra0.y);
                Ahi[r0 + d2] = f2tf32(ra0.z);
                Ahi[r0 + d3] = f2tf32(ra0.w);
                Ahi[r1 + d0] = f2tf32(ra1.x);
                Ahi[r1 + d1] = f2tf32(ra1.y);
                Ahi[r1 + d2] = f2tf32(ra1.z);
                Ahi[r1 + d3] = f2tf32(ra1.w);
                Bhi[r0 + d0] = f2tf32(rb0.x);
                Bhi[r0 + d1] = f2tf32(rb0.y);
                Bhi[r0 + d2] = f2tf32(rb0.z);
                Bhi[r0 + d3] = f2tf32(rb0.w);
                Bhi[r1 + d0] = f2tf32(rb1.x);
                Bhi[r1 + d1] = f2tf32(rb1.y);
                Bhi[r1 + d2] = f2tf32(rb1.z);
                Bhi[r1 + d3] = f2tf32(rb1.w);
            }
            __syncthreads();

            if (kt + BK < Kd) {
                aPtr += BK; wPtr += BK;
                ra0 = *(const float4*)(aPtr);
                ra1 = *(const float4*)(aPtr + (size_t)64 * Kd);
                rb0 = *(const float4*)(wPtr);
                rb1 = *(const float4*)(wPtr + (size_t)64 * Kd);
            }

            // B fragments for the whole 16-k tile: one LDS.128 per nt
            uint4 bq[4];
#pragma unroll
            for (int nt = 0; nt < 4; ++nt)
                bq[nt] = *(const uint4*)&Bhi[(wN * 32 + nt * 8 + g) * SSTR + 4 * q];

#pragma unroll
            for (int mt = 0; mt < 4; ++mt) {
                int r0 = (wM * 64 + mt * 16 + g) * SSTR + 4 * q;
                uint4 ua = *(const uint4*)&Ahi[r0];
                uint4 ub = *(const uint4*)&Ahi[r0 + 8 * SSTR];
#pragma unroll
                for (int nt = 0; nt < 4; ++nt) {
                    float* c = acc[mt][nt];
                    // ks = 0 (k 0..7)
                    mma_tf32(c[0], c[1], c[2], c[3],
                             ua.x, ub.x, ua.y, ub.y, bq[nt].x, bq[nt].y);
                    // ks = 1 (k 8..15)
                    mma_tf32(c[0], c[1], c[2], c[3],
                             ua.z, ub.z, ua.w, ub.w, bq[nt].z, bq[nt].w);
                }
            }
        }
    }

#pragma unroll
    for (int mt = 0; mt < 4; ++mt) {
#pragma unroll
        for (int nt = 0; nt < 4; ++nt) {
            const float* c = acc[mt][nt];
            int row0 = by * BM + wM * 64 + mt * 16 + g;
            int col  = bx * BN + wN * 32 + nt * 8 + 2 * q;
            size_t idx0 = (size_t)row0 * Hd + col;
            size_t idx1 = idx0 + (size_t)8 * Hd;
            float2 i0 = *(const float2*)(iin + idx0);
            float2 i1 = *(const float2*)(iin + idx1);
            float2 o0, o1;
            o0.x = (i0.x - DT_TAU_SYN * i0.x) + c[0];
            o0.y = (i0.y - DT_TAU_SYN * i0.y) + c[1];
            o1.x = (i1.x - DT_TAU_SYN * i1.x) + c[2];
            o1.y = (i1.y - DT_TAU_SYN * i1.y) + c[3];
            *(float2*)(out_i + idx0) = o0;
            *(float2*)(out_i + idx1) = o1;
        }
    }
}

__global__ void __launch_bounds__(NTHREADS, 2) lif_hybrid_kernel(
    const float* __restrict__ inp, const float* __restrict__ z,
    const float* __restrict__ v,   const float* __restrict__ icur,
    const float* __restrict__ rho,
    const float* __restrict__ Wi,  const float* __restrict__ Wr,
    const float* __restrict__ g,
    float* __restrict__ out_z, float* __restrict__ out_v,
    float* __restrict__ out_i, float* __restrict__ out_rho)
{
    __shared__ __align__(16) unsigned char smem_raw[SMEM_BYTES];

    const int bid  = blockIdx.x;
    const int role = (bid >> 2) & 1;     // 148/4 odd -> co-resident CTAs mix roles
    const int sub  = (bid >> 3) * 4 + (bid & 3);
    const int bx = sub & 15;
    const int by = sub >> 4;

    if (role == 0) {
        coupling_simt(smem_raw, bx, by, v, g, v, icur, rho, out_z, out_v, out_rho);
    } else {
        ipath_mma(smem_raw, bx, by, inp, Wi, z, Wr, icur, out_i);
    }
}

extern "C" void kernel_launch(void* const* d_in, const int* in_sizes, int n_in,
                              void* d_out, int out_size)
{
    const float* inp  = (const float*)d_in[0];
    const float* z    = (const float*)d_in[1];
    const float* v    = (const float*)d_in[2];
    const float* icur = (const float*)d_in[3];
    const float* rho  = (const float*)d_in[4];
    const float* Wi   = (const float*)d_in[5];
    const float* Wr   = (const float*)d_in[6];
    const float* g    = (const float*)d_in[7];

    float* out      = (float*)d_out;
    const size_t nBH = (size_t)Bd * Hd;

    lif_hybrid_kernel<<<1024, NTHREADS>>>(
        inp, z, v, icur, rho, Wi, Wr, g,
        out, out + nBH, out + 2 * nBH, out + 3 * nBH);
}

// round 6
// speedup vs baseline: 1.0874x; 1.0874x over previous
#include <cuda_runtime.h>
#include <cstdint>

// LIF-MC-Refrac hybrid kernel (R6):
//   role 0: couple = v @ g.T, packed fp32 FFMA2, 16x16 thread grid, dense-split
//           B column mapping (cols tx*4 and 64+tx*4) -> minimal L1 wavefronts
//           -> z, v, rho epilogue
//   role 1: i_new = i_decayed + inp@Wi.T + z@Wr.T, TF32 mma.sync, LDS.128 frags
//           -> i epilogue

namespace {
constexpr int Bd = 4096;
constexpr int Hd = 2048;
constexpr int Kd = 2048;

constexpr int BM = 128, BN = 128, BK = 16;
constexpr int NTHREADS = 256;
constexpr int SSTR = BK + 4;

constexpr float DT_TAU_MEM = 0.1f;
constexpr float DT_TAU_SYN = 0.2f;
constexpr float V_TH_C     = 1.0f;
constexpr float RHO_RST    = 5.0f;

constexpr int SMEM_BYTES = 2 * 128 * SSTR * 4;
}

// ---- packed f32x2 helpers ----
__device__ __forceinline__ unsigned long long packf2(float lo, float hi) {
    unsigned long long r;
    asm("mov.b64 %0, {%1, %2};" : "=l"(r) : "f"(lo), "f"(hi));
    return r;
}
__device__ __forceinline__ unsigned long long dupf2(float x) {
    unsigned long long r;
    asm("mov.b64 %0, {%1, %1};" : "=l"(r) : "f"(x));
    return r;
}
__device__ __forceinline__ void ffma2(unsigned long long& d,
                                      unsigned long long a, unsigned long long b) {
    asm("fma.rn.f32x2 %0, %1, %2, %0;" : "+l"(d) : "l"(a), "l"(b));
}
__device__ __forceinline__ void unpackf2(unsigned long long v, float& lo, float& hi) {
    asm("mov.b64 {%0, %1}, %2;" : "=f"(lo), "=f"(hi) : "l"(v));
}

__device__ __forceinline__ uint32_t f2tf32(float x) {
    uint32_t r;
    asm("cvt.rna.tf32.f32 %0, %1;" : "=r"(r) : "f"(x));
    return r;
}

__device__ __forceinline__ void mma_tf32(float& c0, float& c1, float& c2, float& c3,
                                         uint32_t a0, uint32_t a1, uint32_t a2, uint32_t a3,
                                         uint32_t b0, uint32_t b1)
{
    asm volatile(
        "mma.sync.aligned.m16n8k8.row.col.f32.tf32.tf32.f32 "
        "{%0,%1,%2,%3},{%4,%5,%6,%7},{%8,%9},{%0,%1,%2,%3};"
        : "+f"(c0), "+f"(c1), "+f"(c2), "+f"(c3)
        : "r"(a0), "r"(a1), "r"(a2), "r"(a3), "r"(b0), "r"(b1));
}

__device__ __forceinline__ void lif_elem(float v, float i, float rho, float couple,
                                         float& z_out, float& v_out, float& rho_out)
{
    float dv    = DT_TAU_MEM * ((0.0f - v) + i);
    float v_dec = (v + dv) + couple;
    float z     = (v_dec - V_TH_C) > 0.0f ? 1.0f : 0.0f;
    float v_new = (1.0f - z) * v_dec;
    float mask  = rho > 0.0f ? 1.0f : 0.0f;
    v_new = (1.0f - mask) * v_new + mask * v;
    z     = (1.0f - mask) * z;
    rho_out = (1.0f - z) * fmaxf(rho - mask, 0.0f) + z * RHO_RST;
    z_out = z;
    v_out = v_new;
}

// ---------------- role 0: packed-fp32 coupling GEMM (dense-split cols) -------
__device__ void coupling_simt(
    unsigned char* smem_raw, int bx, int by,
    const float* __restrict__ A0, const float* __restrict__ W0,
    const float* __restrict__ vin, const float* __restrict__ iin,
    const float* __restrict__ rhoin,
    float* __restrict__ out_z, float* __restrict__ out_v, float* __restrict__ out_rho)
{
    float* As = (float*)smem_raw;                 // [BK][BM+4]
    float* Bs = As + BK * (BM + 4);               // [BK][BN+4]
    constexpr int AST = BM + 4;

    const int tid = threadIdx.x;
    const int tx = tid & 15;     // 16 col groups
    const int ty = tid >> 4;     // 16 row groups
    const int cA = tx * 4;       // dense cols [cA, cA+4)
    const int cB = 64 + tx * 4;  // dense cols [cB, cB+4)

    const int loadRow = tid >> 2;
    const int loadK   = (tid & 3) << 2;

    // acc2[p][b]: rows (ty*8+2p, ty*8+2p+1); b<4 -> col cA+b, b>=4 -> col cB+(b-4)
    unsigned long long acc2[4][8];
#pragma unroll
    for (int a = 0; a < 4; ++a)
#pragma unroll
        for (int b = 0; b < 8; ++b) acc2[a][b] = 0ull;

    const float* aPtr = A0 + (size_t)(by * BM + loadRow) * Kd + loadK;
    const float* wPtr = W0 + (size_t)(bx * BN + loadRow) * Kd + loadK;

    float4 ra0 = *(const float4*)(aPtr);
    float4 ra1 = *(const float4*)(aPtr + (size_t)64 * Kd);
    float4 rb0 = *(const float4*)(wPtr);
    float4 rb1 = *(const float4*)(wPtr + (size_t)64 * Kd);

    for (int kt = 0; kt < Kd; kt += BK) {
        __syncthreads();
        As[(loadK + 0) * AST + loadRow]      = ra0.x;
        As[(loadK + 1) * AST + loadRow]      = ra0.y;
        As[(loadK + 2) * AST + loadRow]      = ra0.z;
        As[(loadK + 3) * AST + loadRow]      = ra0.w;
        As[(loadK + 0) * AST + loadRow + 64] = ra1.x;
        As[(loadK + 1) * AST + loadRow + 64] = ra1.y;
        As[(loadK + 2) * AST + loadRow + 64] = ra1.z;
        As[(loadK + 3) * AST + loadRow + 64] = ra1.w;
        Bs[(loadK + 0) * AST + loadRow]      = rb0.x;
        Bs[(loadK + 1) * AST + loadRow]      = rb0.y;
        Bs[(loadK + 2) * AST + loadRow]      = rb0.z;
        Bs[(loadK + 3) * AST + loadRow]      = rb0.w;
        Bs[(loadK + 0) * AST + loadRow + 64] = rb1.x;
        Bs[(loadK + 1) * AST + loadRow + 64] = rb1.y;
        Bs[(loadK + 2) * AST + loadRow + 64] = rb1.z;
        Bs[(loadK + 3) * AST + loadRow + 64] = rb1.w;
        __syncthreads();

        if (kt + BK < Kd) {
            aPtr += BK; wPtr += BK;
            ra0 = *(const float4*)(aPtr);
            ra1 = *(const float4*)(aPtr + (size_t)64 * Kd);
            rb0 = *(const float4*)(wPtr);
            rb1 = *(const float4*)(wPtr + (size_t)64 * Kd);
        }

#pragma unroll
        for (int k = 0; k < BK; ++k) {
            float4 a0 = *(const float4*)&As[k * AST + ty * 8];
            float4 a1 = *(const float4*)&As[k * AST + ty * 8 + 4];
            // dense-split B: each LDS.128 covers a dense 256B warp region
            float4 b0 = *(const float4*)&Bs[k * AST + cA];
            float4 b1 = *(const float4*)&Bs[k * AST + cB];

            unsigned long long ap[4];
            ap[0] = packf2(a0.x, a0.y);
            ap[1] = packf2(a0.z, a0.w);
            ap[2] = packf2(a1.x, a1.y);
            ap[3] = packf2(a1.z, a1.w);

            float bf[8] = {b0.x, b0.y, b0.z, b0.w, b1.x, b1.y, b1.z, b1.w};
#pragma unroll
            for (int b = 0; b < 8; ++b) {
                unsigned long long bb = dupf2(bf[b]);
                ffma2(acc2[0][b], ap[0], bb);
                ffma2(acc2[1][b], ap[1], bb);
                ffma2(acc2[2][b], ap[2], bb);
                ffma2(acc2[3][b], ap[3], bb);
            }
        }
    }

    float acc[8][8];
#pragma unroll
    for (int p = 0; p < 4; ++p)
#pragma unroll
        for (int b = 0; b < 8; ++b)
            unpackf2(acc2[p][b], acc[2 * p][b], acc[2 * p + 1][b]);

    const int row0  = by * BM + ty * 8;
    const int colA  = bx * BN + cA;
    const int colB  = bx * BN + cB;
#pragma unroll
    for (int a = 0; a < 8; ++a) {
        const size_t baseA = (size_t)(row0 + a) * Hd + colA;
        const size_t baseB = (size_t)(row0 + a) * Hd + colB;
#pragma unroll
        for (int h = 0; h < 2; ++h) {
            const size_t base = h ? baseB : baseA;
            const int boff = h * 4;
            float4 vv = *(const float4*)(vin + base);
            float4 iv = *(const float4*)(iin + base);
            float4 rv = *(const float4*)(rhoin + base);
            float4 oz, ov, orh;
            lif_elem(vv.x, iv.x, rv.x, acc[a][boff + 0], oz.x, ov.x, orh.x);
            lif_elem(vv.y, iv.y, rv.y, acc[a][boff + 1], oz.y, ov.y, orh.y);
            lif_elem(vv.z, iv.z, rv.z, acc[a][boff + 2], oz.z, ov.z, orh.z);
            lif_elem(vv.w, iv.w, rv.w, acc[a][boff + 3], oz.w, ov.w, orh.w);
            *(float4*)(out_z   + base) = oz;
            *(float4*)(out_v   + base) = ov;
            *(float4*)(out_rho + base) = orh;
        }
    }
}

// ---------------- role 1: TF32 MMA i-path, LDS.128 fragment layout ------------
// smem word position within each 16-k row: pos(k) = 4*(k&3) + (k>>2).
// A uint4 at row*SSTR + 4q holds k = {q, q+4, q+8, q+12}: both ks halves of the
// m16n8k8 fragments in ONE LDS.128.
__device__ void ipath_mma(
    unsigned char* smem_raw, int bx, int by,
    const float* __restrict__ A0, const float* __restrict__ W0,
    const float* __restrict__ A1, const float* __restrict__ W1,
    const float* __restrict__ iin, float* __restrict__ out_i)
{
    uint32_t* Ahi = (uint32_t*)smem_raw;
    uint32_t* Bhi = Ahi + BM * SSTR;

    const int tid  = threadIdx.x;
    const int warp = tid >> 5;
    const int lane = tid & 31;
    const int g    = lane >> 2;
    const int q    = lane & 3;
    const int wM   = warp >> 2;
    const int wN   = warp & 3;

    const int loadRow = tid >> 2;
    const int loadK   = (tid & 3) << 2;
    const int t       = tid & 3;

    float acc[4][4][4];
#pragma unroll
    for (int mt = 0; mt < 4; ++mt)
#pragma unroll
        for (int nt = 0; nt < 4; ++nt)
#pragma unroll
            for (int r = 0; r < 4; ++r) acc[mt][nt][r] = 0.0f;

    const int d0 = t, d1 = 4 + t, d2 = 8 + t, d3 = 12 + t;

#pragma unroll
    for (int p = 0; p < 2; ++p) {
        const float* Amat = (p == 0) ? A0 : A1;
        const float* Wmat = (p == 0) ? W0 : W1;
        const float* aPtr = Amat + (size_t)(by * BM + loadRow) * Kd + loadK;
        const float* wPtr = Wmat + (size_t)(bx * BN + loadRow) * Kd + loadK;

        float4 ra0 = *(const float4*)(aPtr);
        float4 ra1 = *(const float4*)(aPtr + (size_t)64 * Kd);
        float4 rb0 = *(const float4*)(wPtr);
        float4 rb1 = *(const float4*)(wPtr + (size_t)64 * Kd);

        for (int kt = 0; kt < Kd; kt += BK) {
            __syncthreads();
            {
                int r0 = loadRow * SSTR;
                int r1 = (loadRow + 64) * SSTR;
                Ahi[r0 + d0] = f2tf32(ra0.x);
                Ahi[r0 + d1] = f2tf32(ra0.y);
                Ahi[r0 + d2] = f2tf32(ra0.z);
                Ahi[r0 + d3] = f2tf32(ra0.w);
                Ahi[r1 + d0] = f2tf32(ra1.x);
                Ahi[r1 + d1] = f2tf32(ra1.y);
                Ahi[r1 + d2] = f2tf32(ra1.z);
                Ahi[r1 + d3] = f2tf32(ra1.w);
                Bhi[r0 + d0] = f2tf32(rb0.x);
                Bhi[r0 + d1] = f2tf32(rb0.y);
                Bhi[r0 + d2] = f2tf32(rb0.z);
                Bhi[r0 + d3] = f2tf32(rb0.w);
                Bhi[r1 + d0] = f2tf32(rb1.x);
                Bhi[r1 + d1] = f2tf32(rb1.y);
                Bhi[r1 + d2] = f2tf32(rb1.z);
                Bhi[r1 + d3] = f2tf32(rb1.w);
            }
            __syncthreads();

            if (kt + BK < Kd) {
                aPtr += BK; wPtr += BK;
                ra0 = *(const float4*)(aPtr);
                ra1 = *(const float4*)(aPtr + (size_t)64 * Kd);
                rb0 = *(const float4*)(wPtr);
                rb1 = *(const float4*)(wPtr + (size_t)64 * Kd);
            }

            uint4 bq[4];
#pragma unroll
            for (int nt = 0; nt < 4; ++nt)
                bq[nt] = *(const uint4*)&Bhi[(wN * 32 + nt * 8 + g) * SSTR + 4 * q];

#pragma unroll
            for (int mt = 0; mt < 4; ++mt) {
                int r0 = (wM * 64 + mt * 16 + g) * SSTR + 4 * q;
                uint4 ua = *(const uint4*)&Ahi[r0];
                uint4 ub = *(const uint4*)&Ahi[r0 + 8 * SSTR];
#pragma unroll
                for (int nt = 0; nt < 4; ++nt) {
                    float* c = acc[mt][nt];
                    mma_tf32(c[0], c[1], c[2], c[3],
                             ua.x, ub.x, ua.y, ub.y, bq[nt].x, bq[nt].y);
                    mma_tf32(c[0], c[1], c[2], c[3],
                             ua.z, ub.z, ua.w, ub.w, bq[nt].z, bq[nt].w);
                }
            }
        }
    }

#pragma unroll
    for (int mt = 0; mt < 4; ++mt) {
#pragma unroll
        for (int nt = 0; nt < 4; ++nt) {
            const float* c = acc[mt][nt];
            int row0 = by * BM + wM * 64 + mt * 16 + g;
            int col  = bx * BN + wN * 32 + nt * 8 + 2 * q;
            size_t idx0 = (size_t)row0 * Hd + col;
            size_t idx1 = idx0 + (size_t)8 * Hd;
            float2 i0 = *(const float2*)(iin + idx0);
            float2 i1 = *(const float2*)(iin + idx1);
            float2 o0, o1;
            o0.x = (i0.x - DT_TAU_SYN * i0.x) + c[0];
            o0.y = (i0.y - DT_TAU_SYN * i0.y) + c[1];
            o1.x = (i1.x - DT_TAU_SYN * i1.x) + c[2];
            o1.y = (i1.y - DT_TAU_SYN * i1.y) + c[3];
            *(float2*)(out_i + idx0) = o0;
            *(float2*)(out_i + idx1) = o1;
        }
    }
}

__global__ void __launch_bounds__(NTHREADS, 2) lif_hybrid_kernel(
    const float* __restrict__ inp, const float* __restrict__ z,
    const float* __restrict__ v,   const float* __restrict__ icur,
    const float* __restrict__ rho,
    const float* __restrict__ Wi,  const float* __restrict__ Wr,
    const float* __restrict__ g,
    float* __restrict__ out_z, float* __restrict__ out_v,
    float* __restrict__ out_i, float* __restrict__ out_rho)
{
    __shared__ __align__(16) unsigned char smem_raw[SMEM_BYTES];

    const int bid  = blockIdx.x;
    const int role = (bid >> 2) & 1;
    const int sub  = (bid >> 3) * 4 + (bid & 3);
    const int bx = sub & 15;
    const int by = sub >> 4;

    if (role == 0) {
        coupling_simt(smem_raw, bx, by, v, g, v, icur, rho, out_z, out_v, out_rho);
    } else {
        ipath_mma(smem_raw, bx, by, inp, Wi, z, Wr, icur, out_i);
    }
}

extern "C" void kernel_launch(void* const* d_in, const int* in_sizes, int n_in,
                              void* d_out, int out_size)
{
    const float* inp  = (const float*)d_in[0];
    const float* z    = (const float*)d_in[1];
    const float* v    = (const float*)d_in[2];
    const float* icur = (const float*)d_in[3];
    const float* rho  = (const float*)d_in[4];
    const float* Wi   = (const float*)d_in[5];
    const float* Wr   = (const float*)d_in[6];
    const float* g    = (const float*)d_in[7];

    float* out      = (float*)d_out;
    const size_t nBH = (size_t)Bd * Hd;

    lif_hybrid_kernel<<<1024, NTHREADS>>>(
        inp, z, v, icur, rho, Wi, Wr, g,
        out, out + nBH, out + 2 * nBH, out + 3 * nBH);
}

// round 8
// speedup vs baseline: 1.2861x; 1.1827x over previous
#include <cuda_runtime.h>
#include <cstdint>

// LIF-MC-Refrac hybrid (R8) = R4 base +
//  - coupling: dense-split B cols (tx*4 / 64+tx*4) -> dense L1 wavefronts
//  - i-path: raw fp32 -> tf32 truncation (no CVT), R4 kperm fragment layout
//  AST back to 132 (R7's 130 broke LDS.128 alignment).

namespace {
constexpr int Bd = 4096;
constexpr int Hd = 2048;
constexpr int Kd = 2048;

constexpr int BM = 128, BN = 128, BK = 16;
constexpr int NTHREADS = 256;
constexpr int SSTR = BK + 4;          // mma smem row stride (words)
constexpr int AST  = BM + 4;          // 132: row stride 528B, 16B-aligned

constexpr float DT_TAU_MEM = 0.1f;
constexpr float DT_TAU_SYN = 0.2f;
constexpr float V_TH_C     = 1.0f;
constexpr float RHO_RST    = 5.0f;

constexpr int SMEM_BYTES = 2 * 128 * SSTR * 4;   // 20480 >= simt 16896
}

// ---- packed f32x2 helpers ----
__device__ __forceinline__ unsigned long long packf2(float lo, float hi) {
    unsigned long long r;
    asm("mov.b64 %0, {%1, %2};" : "=l"(r) : "f"(lo), "f"(hi));
    return r;
}
__device__ __forceinline__ unsigned long long dupf2(float x) {
    unsigned long long r;
    asm("mov.b64 %0, {%1, %1};" : "=l"(r) : "f"(x));
    return r;
}
__device__ __forceinline__ void ffma2(unsigned long long& d,
                                      unsigned long long a, unsigned long long b) {
    asm("fma.rn.f32x2 %0, %1, %2, %0;" : "+l"(d) : "l"(a), "l"(b));
}
__device__ __forceinline__ void unpackf2(unsigned long long v, float& lo, float& hi) {
    asm("mov.b64 {%0, %1}, %2;" : "=f"(lo), "=f"(hi) : "l"(v));
}

__device__ __forceinline__ void mma_tf32(float& c0, float& c1, float& c2, float& c3,
                                         uint32_t a0, uint32_t a1, uint32_t a2, uint32_t a3,
                                         uint32_t b0, uint32_t b1)
{
    asm volatile(
        "mma.sync.aligned.m16n8k8.row.col.f32.tf32.tf32.f32 "
        "{%0,%1,%2,%3},{%4,%5,%6,%7},{%8,%9},{%0,%1,%2,%3};"
        : "+f"(c0), "+f"(c1), "+f"(c2), "+f"(c3)
        : "r"(a0), "r"(a1), "r"(a2), "r"(a3), "r"(b0), "r"(b1));
}

__device__ __forceinline__ void lif_elem(float v, float i, float rho, float couple,
                                         float& z_out, float& v_out, float& rho_out)
{
    float dv    = DT_TAU_MEM * ((0.0f - v) + i);
    float v_dec = (v + dv) + couple;
    float z     = (v_dec - V_TH_C) > 0.0f ? 1.0f : 0.0f;
    float v_new = (1.0f - z) * v_dec;
    float mask  = rho > 0.0f ? 1.0f : 0.0f;
    v_new = (1.0f - mask) * v_new + mask * v;
    z     = (1.0f - mask) * z;
    rho_out = (1.0f - z) * fmaxf(rho - mask, 0.0f) + z * RHO_RST;
    z_out = z;
    v_out = v_new;
}

__device__ __forceinline__ int kperm(int k) {
    return ((k & 3) << 1) | ((k >> 2) & 1) | (k & 8);
}

// ---------------- role 0: packed-fp32 coupling GEMM ---------------------------
__device__ void coupling_simt(
    unsigned char* smem_raw, int bx, int by,
    const float* __restrict__ A0, const float* __restrict__ W0,
    const float* __restrict__ vin, const float* __restrict__ iin,
    const float* __restrict__ rhoin,
    float* __restrict__ out_z, float* __restrict__ out_v, float* __restrict__ out_rho)
{
    float* As = (float*)smem_raw;                 // [BK][AST]
    float* Bs = As + BK * AST;                    // [BK][AST]

    const int tid = threadIdx.x;
    const int tx = tid & 15;
    const int ty = tid >> 4;
    const int cA = tx * 4;        // dense cols [cA, cA+4)
    const int cB = 64 + tx * 4;   // dense cols [cB, cB+4)

    const int loadRow = tid >> 2;
    const int loadK   = (tid & 3) << 2;

    unsigned long long acc2[4][8];
#pragma unroll
    for (int a = 0; a < 4; ++a)
#pragma unroll
        for (int b = 0; b < 8; ++b) acc2[a][b] = 0ull;

    const float* aPtr = A0 + (size_t)(by * BM + loadRow) * Kd + loadK;
    const float* wPtr = W0 + (size_t)(bx * BN + loadRow) * Kd + loadK;

    float4 ra0 = *(const float4*)(aPtr);
    float4 ra1 = *(const float4*)(aPtr + (size_t)64 * Kd);
    float4 rb0 = *(const float4*)(wPtr);
    float4 rb1 = *(const float4*)(wPtr + (size_t)64 * Kd);

    for (int kt = 0; kt < Kd; kt += BK) {
        __syncthreads();
        As[(loadK + 0) * AST + loadRow]      = ra0.x;
        As[(loadK + 1) * AST + loadRow]      = ra0.y;
        As[(loadK + 2) * AST + loadRow]      = ra0.z;
        As[(loadK + 3) * AST + loadRow]      = ra0.w;
        As[(loadK + 0) * AST + loadRow + 64] = ra1.x;
        As[(loadK + 1) * AST + loadRow + 64] = ra1.y;
        As[(loadK + 2) * AST + loadRow + 64] = ra1.z;
        As[(loadK + 3) * AST + loadRow + 64] = ra1.w;
        Bs[(loadK + 0) * AST + loadRow]      = rb0.x;
        Bs[(loadK + 1) * AST + loadRow]      = rb0.y;
        Bs[(loadK + 2) * AST + loadRow]      = rb0.z;
        Bs[(loadK + 3) * AST + loadRow]      = rb0.w;
        Bs[(loadK + 0) * AST + loadRow + 64] = rb1.x;
        Bs[(loadK + 1) * AST + loadRow + 64] = rb1.y;
        Bs[(loadK + 2) * AST + loadRow + 64] = rb1.z;
        Bs[(loadK + 3) * AST + loadRow + 64] = rb1.w;
        __syncthreads();

        if (kt + BK < Kd) {
            aPtr += BK; wPtr += BK;
            ra0 = *(const float4*)(aPtr);
            ra1 = *(const float4*)(aPtr + (size_t)64 * Kd);
            rb0 = *(const float4*)(wPtr);
            rb1 = *(const float4*)(wPtr + (size_t)64 * Kd);
        }

#pragma unroll
        for (int k = 0; k < BK; ++k) {
            float4 a0 = *(const float4*)&As[k * AST + ty * 8];
            float4 a1 = *(const float4*)&As[k * AST + ty * 8 + 4];
            float4 b0 = *(const float4*)&Bs[k * AST + cA];
            float4 b1 = *(const float4*)&Bs[k * AST + cB];

            unsigned long long ap[4];
            ap[0] = packf2(a0.x, a0.y);
            ap[1] = packf2(a0.z, a0.w);
            ap[2] = packf2(a1.x, a1.y);
            ap[3] = packf2(a1.z, a1.w);

            float bf[8] = {b0.x, b0.y, b0.z, b0.w, b1.x, b1.y, b1.z, b1.w};
#pragma unroll
            for (int b = 0; b < 8; ++b) {
                unsigned long long bb = dupf2(bf[b]);
                ffma2(acc2[0][b], ap[0], bb);
                ffma2(acc2[1][b], ap[1], bb);
                ffma2(acc2[2][b], ap[2], bb);
                ffma2(acc2[3][b], ap[3], bb);
            }
        }
    }

    float acc[8][8];
#pragma unroll
    for (int p = 0; p < 4; ++p)
#pragma unroll
        for (int b = 0; b < 8; ++b)
            unpackf2(acc2[p][b], acc[2 * p][b], acc[2 * p + 1][b]);

    const int row0 = by * BM + ty * 8;
    const int colA = bx * BN + cA;
    const int colB = bx * BN + cB;
#pragma unroll
    for (int a = 0; a < 8; ++a) {
#pragma unroll
        for (int h = 0; h < 2; ++h) {
            const size_t base = (size_t)(row0 + a) * Hd + (h ? colB : colA);
            const int boff = h * 4;
            float4 vv = *(const float4*)(vin + base);
            float4 iv = *(const float4*)(iin + base);
            float4 rv = *(const float4*)(rhoin + base);
            float4 oz, ov, orh;
            lif_elem(vv.x, iv.x, rv.x, acc[a][boff + 0], oz.x, ov.x, orh.x);
            lif_elem(vv.y, iv.y, rv.y, acc[a][boff + 1], oz.y, ov.y, orh.y);
            lif_elem(vv.z, iv.z, rv.z, acc[a][boff + 2], oz.z, ov.z, orh.z);
            lif_elem(vv.w, iv.w, rv.w, acc[a][boff + 3], oz.w, ov.w, orh.w);
            *(float4*)(out_z   + base) = oz;
            *(float4*)(out_v   + base) = ov;
            *(float4*)(out_rho + base) = orh;
        }
    }
}

// ---------------- role 1: TF32 MMA i-path (R4 kperm layout, no CVT) -----------
__device__ void ipath_mma(
    unsigned char* smem_raw, int bx, int by,
    const float* __restrict__ A0, const float* __restrict__ W0,
    const float* __restrict__ A1, const float* __restrict__ W1,
    const float* __restrict__ iin, float* __restrict__ out_i)
{
    uint32_t* Ahi = (uint32_t*)smem_raw;
    uint32_t* Bhi = Ahi + BM * SSTR;

    const int tid  = threadIdx.x;
    const int warp = tid >> 5;
    const int lane = tid & 31;
    const int g    = lane >> 2;
    const int q    = lane & 3;
    const int wM   = warp >> 2;
    const int wN   = warp & 3;

    const int loadRow = tid >> 2;
    const int loadK   = (tid & 3) << 2;

    float acc[4][4][4];
#pragma unroll
    for (int mt = 0; mt < 4; ++mt)
#pragma unroll
        for (int nt = 0; nt < 4; ++nt)
#pragma unroll
            for (int r = 0; r < 4; ++r) acc[mt][nt][r] = 0.0f;

    int d0 = kperm(loadK + 0), d1 = kperm(loadK + 1),
        d2 = kperm(loadK + 2), d3 = kperm(loadK + 3);

#pragma unroll
    for (int p = 0; p < 2; ++p) {
        const float* Amat = (p == 0) ? A0 : A1;
        const float* Wmat = (p == 0) ? W0 : W1;
        const float* aPtr = Amat + (size_t)(by * BM + loadRow) * Kd + loadK;
        const float* wPtr = Wmat + (size_t)(bx * BN + loadRow) * Kd + loadK;

        // raw fp32 bits; tensor core truncates to tf32 (error ~2^-11, fine for i)
        uint4 ra0 = *(const uint4*)(aPtr);
        uint4 ra1 = *(const uint4*)(aPtr + (size_t)64 * Kd);
        uint4 rb0 = *(const uint4*)(wPtr);
        uint4 rb1 = *(const uint4*)(wPtr + (size_t)64 * Kd);

        for (int kt = 0; kt < Kd; kt += BK) {
            __syncthreads();
            {
                int r0 = loadRow * SSTR;
                int r1 = (loadRow + 64) * SSTR;
                Ahi[r0 + d0] = ra0.x;
                Ahi[r0 + d1] = ra0.y;
                Ahi[r0 + d2] = ra0.z;
                Ahi[r0 + d3] = ra0.w;
                Ahi[r1 + d0] = ra1.x;
                Ahi[r1 + d1] = ra1.y;
                Ahi[r1 + d2] = ra1.z;
                Ahi[r1 + d3] = ra1.w;
                Bhi[r0 + d0] = rb0.x;
                Bhi[r0 + d1] = rb0.y;
                Bhi[r0 + d2] = rb0.z;
                Bhi[r0 + d3] = rb0.w;
                Bhi[r1 + d0] = rb1.x;
                Bhi[r1 + d1] = rb1.y;
                Bhi[r1 + d2] = rb1.z;
                Bhi[r1 + d3] = rb1.w;
            }
            __syncthreads();

            if (kt + BK < Kd) {
                aPtr += BK; wPtr += BK;
                ra0 = *(const uint4*)(aPtr);
                ra1 = *(const uint4*)(aPtr + (size_t)64 * Kd);
                rb0 = *(const uint4*)(wPtr);
                rb1 = *(const uint4*)(wPtr + (size_t)64 * Kd);
            }

#pragma unroll
            for (int ks = 0; ks < 2; ++ks) {
                const int kb = ks * 8 + 2 * q;
                uint32_t bh[4][2];
#pragma unroll
                for (int nt = 0; nt < 4; ++nt) {
                    int bidx = (wN * 32 + nt * 8 + g) * SSTR + kb;
                    uint2 t = *(const uint2*)&Bhi[bidx];
                    bh[nt][0] = t.x; bh[nt][1] = t.y;
                }
#pragma unroll
                for (int mt = 0; mt < 4; ++mt) {
                    int r0 = (wM * 64 + mt * 16 + g) * SSTR + kb;
                    int r1 = r0 + 8 * SSTR;
                    uint2 ta = *(const uint2*)&Ahi[r0];
                    uint2 tb = *(const uint2*)&Ahi[r1];
#pragma unroll
                    for (int nt = 0; nt < 4; ++nt) {
                        float* c = acc[mt][nt];
                        mma_tf32(c[0], c[1], c[2], c[3],
                                 ta.x, tb.x, ta.y, tb.y, bh[nt][0], bh[nt][1]);
                    }
                }
            }
        }
    }

#pragma unroll
    for (int mt = 0; mt < 4; ++mt) {
#pragma unroll
        for (int nt = 0; nt < 4; ++nt) {
            const float* c = acc[mt][nt];
            int row0 = by * BM + wM * 64 + mt * 16 + g;
            int col  = bx * BN + wN * 32 + nt * 8 + 2 * q;
            size_t idx0 = (size_t)row0 * Hd + col;
            size_t idx1 = idx0 + (size_t)8 * Hd;
            float2 i0 = *(const float2*)(iin + idx0);
            float2 i1 = *(const float2*)(iin + idx1);
            float2 o0, o1;
            o0.x = (i0.x - DT_TAU_SYN * i0.x) + c[0];
            o0.y = (i0.y - DT_TAU_SYN * i0.y) + c[1];
            o1.x = (i1.x - DT_TAU_SYN * i1.x) + c[2];
            o1.y = (i1.y - DT_TAU_SYN * i1.y) + c[3];
            *(float2*)(out_i + idx0) = o0;
            *(float2*)(out_i + idx1) = o1;
        }
    }
}

__global__ void __launch_bounds__(NTHREADS, 2) lif_hybrid_kernel(
    const float* __restrict__ inp, const float* __restrict__ z,
    const float* __restrict__ v,   const float* __restrict__ icur,
    const float* __restrict__ rho,
    const float* __restrict__ Wi,  const float* __restrict__ Wr,
    const float* __restrict__ g,
    float* __restrict__ out_z, float* __restrict__ out_v,
    float* __restrict__ out_i, float* __restrict__ out_rho)
{
    __shared__ __align__(16) unsigned char smem_raw[SMEM_BYTES];

    const int bid  = blockIdx.x;
    const int role = (bid >> 2) & 1;     // co-resident CTAs mix roles
    const int sub  = (bid >> 3) * 4 + (bid & 3);
    const int bx = sub & 15;
    const int by = sub >> 4;

    if (role == 0) {
        coupling_simt(smem_raw, bx, by, v, g, v, icur, rho, out_z, out_v, out_rho);
    } else {
        ipath_mma(smem_raw, bx, by, inp, Wi, z, Wr, icur, out_i);
    }
}

extern "C" void kernel_launch(void* const* d_in, const int* in_sizes, int n_in,
                              void* d_out, int out_size)
{
    const float* inp  = (const float*)d_in[0];
    const float* z    = (const float*)d_in[1];
    const float* v    = (const float*)d_in[2];
    const float* icur = (const float*)d_in[3];
    const float* rho  = (const float*)d_in[4];
    const float* Wi   = (const float*)d_in[5];
    const float* Wr   = (const float*)d_in[6];
    const float* g    = (const float*)d_in[7];

    float* out      = (float*)d_out;
    const size_t nBH = (size_t)Bd * Hd;

    lif_hybrid_kernel<<<1024, NTHREADS>>>(
        inp, z, v, icur, rho, Wi, Wr, g,
        out, out + nBH, out + 2 * nBH, out + 3 * nBH);
}